// round 14
// baseline (speedup 1.0000x reference)
#include <cuda_runtime.h>
#include <cuda_bf16.h>
#include <stdint.h>

// Problem constants (match reference setup_inputs)
#define BATCH 4
#define SEQ   4096
#define ROWS  (BATCH * SEQ)     // 16384
#define CAP   128               // max stored neighbors per row (mean ~41)
#define DT_C  0.1f
#define EPS_C 1e-8f

#define TPB   1024              // 32 warps per block
#define RPB   128               // rows per block (4 rows per warp in sparsify)
#define NBLK  (ROWS / RPB)      // 128 blocks <= 148 SMs: single wave, barrier safe
#define BLK_PER_BATCH (NBLK / BATCH)  // 32 blocks per batch
#define NBAR  5                 // barriers per call (round-robin counters)
#define NREG  10                // per-sub-thread register col cache (covers cnt<=80)

// Persistent scratch (no allocations allowed)
__device__ uint16_t g_cols[ROWS * CAP];       // 4 MB: [row][pos]
__device__ float2   g_psi[ROWS];              // state published between steps
__device__ float2   g_star[ROWS];             // psi_star published between phases
__device__ unsigned g_bars[BATCH][NBAR];      // zero-init; self-resetting round-robin

// ---------------------------------------------------------------------------
// Memory helpers
// ---------------------------------------------------------------------------
__device__ __forceinline__ float4 ldcg_f4(const float4* p) {
    float4 v;
    asm volatile("ld.global.cg.v4.f32 {%0,%1,%2,%3}, [%4];"
                 : "=f"(v.x), "=f"(v.y), "=f"(v.z), "=f"(v.w) : "l"(p));
    return v;
}
__device__ __forceinline__ float4 ldcs_f4(const float4* p) {  // evict-first stream
    float4 v;
    asm volatile("ld.global.cs.v4.f32 {%0,%1,%2,%3}, [%4];"
                 : "=f"(v.x), "=f"(v.y), "=f"(v.z), "=f"(v.w) : "l"(p));
    return v;
}
__device__ __forceinline__ unsigned ld_acquire_gpu(const unsigned* p) {
    unsigned v;
    asm volatile("ld.acquire.gpu.u32 %0, [%1];" : "=r"(v) : "l"(p) : "memory");
    return v;
}
__device__ __forceinline__ void red_add_release_gpu(unsigned* p, unsigned v) {
    asm volatile("red.add.release.gpu.u32 [%0], %1;" :: "l"(p), "r"(v) : "memory");
}
__device__ __forceinline__ void st_release_gpu(unsigned* p, unsigned v) {
    asm volatile("st.release.gpu.u32 [%0], %1;" :: "l"(p), "r"(v) : "memory");
}

// ---------------------------------------------------------------------------
// Per-batch barrier, fixed target, self-resetting round-robin counters.
// After passing barrier b, the batch's designated block resets counter
// (b-1) mod NBAR: all 32 arrivals at b imply no block will poll b-1 again
// this call; the release-add / acquire-load chain orders the reset before
// any later add to that counter (incl. next call via kernel boundary).
// No __threadfence anywhere -> no CCTL.IVALL -> L1 survives across phases.
// ---------------------------------------------------------------------------
__device__ __forceinline__ void batch_barrier(unsigned* bars, int b, bool designated) {
    __syncthreads();
    if (threadIdx.x == 0) {
        red_add_release_gpu(&bars[b], 1u);
        while (ld_acquire_gpu(&bars[b]) < BLK_PER_BATCH) { /* poll */ }
        if (designated) st_release_gpu(&bars[(b + NBAR - 1) % NBAR], 0u);
    }
    __syncthreads();
}

// ---------------------------------------------------------------------------
// ONE persistent kernel: sparsify(+k1/star of step 0) then 5 phases
// (B0, A1, B1, A2, B2) with 5 per-batch barriers (incl. post-A0).
// ---------------------------------------------------------------------------
__global__ void __launch_bounds__(TPB) radial_kernel(const float2* __restrict__ psi_in,
                                                     const float4* __restrict__ mask,
                                                     float2* __restrict__ out) {
    __shared__ float2 sstate[SEQ];     // 32 KB: batch state for gathers
    __shared__ float2 s_k1[RPB];
    __shared__ float2 s_star[RPB];
    __shared__ float  s_r[RPB];
    __shared__ int    s_cnt[RPB];

    const int tid     = threadIdx.x;
    const int lane    = tid & 31;
    const int wid     = tid >> 5;
    const int rowbase = blockIdx.x * RPB;
    const int batch   = rowbase >> 12;                  // blockIdx.x / 32
    const bool designated = ((blockIdx.x & (BLK_PER_BATCH - 1)) == 0);
    unsigned* bars = g_bars[batch];

    const float2* __restrict__ bpsi_in = psi_in + (size_t)batch * SEQ;
    const float4* __restrict__ bpsi4   = (const float4*)(g_psi  + (size_t)batch * SEQ);
    const float4* __restrict__ bstar4  = (const float4*)(g_star + (size_t)batch * SEQ);
    float4* __restrict__ sstate4       = (float4*)sstate;

    // ---- Stage psi_in (batch) into smem for the k1 gathers ----
#pragma unroll
    for (int i = 0; i < SEQ / 2 / TPB; i++)
        sstate4[tid + i * TPB] = ((const float4*)bpsi_in)[tid + i * TPB];
    __syncthreads();

    // ================= Phase A0: sparsify + k1 + psi_star =================
    // Each warp streams 4 rows' mask (16KB each) with depth-2 prefetch,
    // compacts columns via warp scan (deterministic order), gathers psi
    // from smem on the fly, and emits k1/r/star for its rows.
#pragma unroll 1
    for (int rr = 0; rr < 4; rr++) {
        const int lrow = wid * 4 + rr;                 // 0..127
        const int row  = rowbase + lrow;
        const float4* rp = mask + (size_t)row * (SEQ / 4);
        uint16_t* outc = g_cols + (size_t)row * CAP;

        float4 buf0 = ldcs_f4(&rp[lane]);
        float4 buf1 = ldcs_f4(&rp[lane + 32]);

        int offset = 0;
        float sx = 0.0f, sy = 0.0f;
#pragma unroll 1
        for (int it = 0; it < 32; it++) {
            float4 cur = buf0;
            buf0 = buf1;
            if (it < 30) buf1 = ldcs_f4(&rp[lane + (it + 2) * 32]);

            const int base = (lane + it * 32) * 4;
            int c = (cur.x != 0.0f) + (cur.y != 0.0f) +
                    (cur.z != 0.0f) + (cur.w != 0.0f);

            // warp exclusive scan of c
            int inc = c;
#pragma unroll
            for (int o = 1; o < 32; o <<= 1) {
                int n = __shfl_up_sync(0xFFFFFFFFu, inc, o);
                if (lane >= o) inc += n;
            }
            int tot = __shfl_sync(0xFFFFFFFFu, inc, 31);
            int pos = offset + (inc - c);

            if (cur.x != 0.0f) { float2 v = sstate[base + 0]; sx += v.x; sy += v.y;
                                 if (pos < CAP) outc[pos] = (uint16_t)(base + 0); pos++; }
            if (cur.y != 0.0f) { float2 v = sstate[base + 1]; sx += v.x; sy += v.y;
                                 if (pos < CAP) outc[pos] = (uint16_t)(base + 1); pos++; }
            if (cur.z != 0.0f) { float2 v = sstate[base + 2]; sx += v.x; sy += v.y;
                                 if (pos < CAP) outc[pos] = (uint16_t)(base + 2); pos++; }
            if (cur.w != 0.0f) { float2 v = sstate[base + 3]; sx += v.x; sy += v.y;
                                 if (pos < CAP) outc[pos] = (uint16_t)(base + 3); pos++; }
            offset += tot;
        }

        // warp reduce the force sum (fixed order -> deterministic)
#pragma unroll
        for (int o = 16; o; o >>= 1) {
            sx += __shfl_xor_sync(0xFFFFFFFFu, sx, o);
            sy += __shfl_xor_sync(0xFFFFFFFFu, sy, o);
        }
        if (lane == 0) {
            float2 p = bpsi_in[row - (size_t)batch * SEQ];
            float k1x = sx - p.x, k1y = sy - p.y;
            float r = sqrtf(p.x * p.x + p.y * p.y);
            float stx = p.x + DT_C * k1x;
            float sty = p.y + DT_C * k1y;
            float sn = sqrtf(stx * stx + sty * sty);
            float sc = r / (sn + EPS_C);
            float2 star = make_float2(stx * sc, sty * sc);
            g_star[row]   = star;                      // publish for the batch
            s_star[lrow]  = star;
            s_k1[lrow]    = make_float2(k1x, k1y);
            s_r[lrow]     = r;
            s_cnt[lrow]   = (offset < CAP) ? offset : CAP;
        }
    }

    batch_barrier(bars, 0, designated);   // all batch psi_star published

    // ---- switch to 8-threads-per-row layout for the integration phases ----
    const int lrow = tid >> 3;                         // 0..127
    const int row  = rowbase + lrow;
    const int sub  = tid & 7;

    const int cnt = s_cnt[lrow];
    const uint16_t* __restrict__ cols = g_cols + (size_t)row * CAP;

    int myc[NREG];                                     // register col cache
#pragma unroll
    for (int k = 0; k < NREG; k++) {
        int i = sub + 8 * k;
        myc[k] = (i < cnt) ? (int)cols[i] : 0;
    }

    float2 p    = bpsi_in[lrow + (rowbase & (SEQ - 1))]; // psi_in[row]
    float2 k1   = s_k1[lrow];
    float2 star = s_star[lrow];
    float  r    = s_r[lrow];
    int    bidx = 1;

#pragma unroll 1
    for (int s = 0; s < 3; s++) {
        if (s > 0) {
            // ---------- Phase A: stage g_psi, k1 = force(p), psi_star ----------
#pragma unroll
            for (int i = 0; i < SEQ / 2 / TPB; i++)
                sstate4[tid + i * TPB] = ldcg_f4(&bpsi4[tid + i * TPB]);
            __syncthreads();

            float sx = 0.0f, sy = 0.0f;
#pragma unroll
            for (int k = 0; k < NREG; k++) {
                if (sub + 8 * k < cnt) {
                    float2 v = sstate[myc[k]];
                    sx += v.x; sy += v.y;
                }
            }
            for (int i = sub + 8 * NREG; i < cnt; i += 8) {   // rare tail
                float2 v = sstate[cols[i]];
                sx += v.x; sy += v.y;
            }
            sx += __shfl_xor_sync(0xFFFFFFFFu, sx, 1);
            sy += __shfl_xor_sync(0xFFFFFFFFu, sy, 1);
            sx += __shfl_xor_sync(0xFFFFFFFFu, sx, 2);
            sy += __shfl_xor_sync(0xFFFFFFFFu, sy, 2);
            sx += __shfl_xor_sync(0xFFFFFFFFu, sx, 4);
            sy += __shfl_xor_sync(0xFFFFFFFFu, sy, 4);

            k1.x = sx - p.x; k1.y = sy - p.y;
            r = sqrtf(p.x * p.x + p.y * p.y);
            float stx = p.x + DT_C * k1.x;
            float sty = p.y + DT_C * k1.y;
            float sn = sqrtf(stx * stx + sty * sty);
            float sc = r / (sn + EPS_C);
            star = make_float2(stx * sc, sty * sc);
            if (sub == 0) g_star[row] = star;

            batch_barrier(bars, bidx++, designated);
        }

        // ---------- Phase B: stage g_star, k2 = force(star), update p ----------
#pragma unroll
        for (int i = 0; i < SEQ / 2 / TPB; i++)
            sstate4[tid + i * TPB] = ldcg_f4(&bstar4[tid + i * TPB]);
        __syncthreads();

        float sx = 0.0f, sy = 0.0f;
#pragma unroll
        for (int k = 0; k < NREG; k++) {
            if (sub + 8 * k < cnt) {
                float2 v = sstate[myc[k]];
                sx += v.x; sy += v.y;
            }
        }
        for (int i = sub + 8 * NREG; i < cnt; i += 8) {       // rare tail
            float2 v = sstate[cols[i]];
            sx += v.x; sy += v.y;
        }
        sx += __shfl_xor_sync(0xFFFFFFFFu, sx, 1);
        sy += __shfl_xor_sync(0xFFFFFFFFu, sy, 1);
        sx += __shfl_xor_sync(0xFFFFFFFFu, sx, 2);
        sy += __shfl_xor_sync(0xFFFFFFFFu, sy, 2);
        sx += __shfl_xor_sync(0xFFFFFFFFu, sx, 4);
        sy += __shfl_xor_sync(0xFFFFFFFFu, sy, 4);

        float k2x = sx - star.x, k2y = sy - star.y;
        float px = p.x + 0.5f * DT_C * (k1.x + k2x);
        float py = p.y + 0.5f * DT_C * (k1.y + k2y);
        float nn = sqrtf(px * px + py * py);
        float sc2 = r / (nn + EPS_C);
        p = make_float2(px * sc2, py * sc2);

        if (s == 2) {
            if (sub == 0) out[row] = p;        // final result, no barrier needed
        } else {
            if (sub == 0) g_psi[row] = p;      // publish for next step
            batch_barrier(bars, bidx++, designated);
        }
    }
}

extern "C" void kernel_launch(void* const* d_in, const int* in_sizes, int n_in,
                              void* d_out, int out_size) {
    // metadata order: psi (32768 floats), binary_mask (67108864 floats).
    int pi = 0, mi = 1;
    if (n_in >= 2 && in_sizes[0] > in_sizes[1]) { pi = 1; mi = 0; }

    const float2* psi_in = (const float2*)d_in[pi];
    const float4* mask   = (const float4*)d_in[mi];
    float2* out          = (float2*)d_out;

    radial_kernel<<<NBLK, TPB>>>(psi_in, mask, out);
}

// round 15
// speedup vs baseline: 1.4887x; 1.4887x over previous
#include <cuda_runtime.h>
#include <cuda_bf16.h>
#include <stdint.h>

// Problem constants (match reference setup_inputs)
#define BATCH 4
#define SEQ   4096
#define ROWS  (BATCH * SEQ)     // 16384
#define CAP   128               // max stored neighbors per row (mean ~41)
#define DT_C  0.1f
#define EPS_C 1e-8f

#define TPB   1024              // 8 threads per row -> 128 rows/block, 32 warps/SM
#define RPB   (TPB / 8)         // 128 rows per block
#define NBLK  (ROWS / RPB)      // 128 blocks <= 148 SMs: single wave, barrier safe
#define BLK_PER_BATCH (NBLK / BATCH)  // 32 blocks per batch

#define NREG  10                // per-sub-thread register col cache: covers cnt <= 80

// Scratch (no allocations allowed)
__device__ uint16_t g_cols[ROWS * CAP];   // 4 MB, row-contiguous: [row][pos]
__device__ int      g_cnt[ROWS];          // nnz per row
__device__ float2   g_psi[ROWS];          // state published between steps
__device__ float2   g_star[ROWS];         // psi_star published between phases
__device__ unsigned g_bars[BATCH];        // per-batch monotonic barrier counters

// ---------------------------------------------------------------------------
// Memory helpers
// ---------------------------------------------------------------------------
__device__ __forceinline__ float4 ldcg_f4(const float4* p) {
    float4 v;
    asm volatile("ld.global.cg.v4.f32 {%0,%1,%2,%3}, [%4];"
                 : "=f"(v.x), "=f"(v.y), "=f"(v.z), "=f"(v.w) : "l"(p));
    return v;
}
__device__ __forceinline__ float4 ldcs_f4(const float4* p) {  // evict-first stream
    float4 v;
    asm volatile("ld.global.cs.v4.f32 {%0,%1,%2,%3}, [%4];"
                 : "=f"(v.x), "=f"(v.y), "=f"(v.z), "=f"(v.w) : "l"(p));
    return v;
}
__device__ __forceinline__ unsigned ld_acquire_gpu(const unsigned* p) {
    unsigned v;
    asm volatile("ld.acquire.gpu.u32 %0, [%1];" : "=r"(v) : "l"(p) : "memory");
    return v;
}
__device__ __forceinline__ void red_add_release_gpu(unsigned* p, unsigned v) {
    asm volatile("red.add.release.gpu.u32 [%0], %1;" :: "l"(p), "r"(v) : "memory");
}

// ---------------------------------------------------------------------------
// Per-batch grid barrier, canonical CG grid.sync pattern. NO __threadfence
// (no CCTL.IVALL -> L1 survives across phases). bar.sync orders the block's
// stores before thread 0's release-RED; acquire-load + bar.sync orders reads.
// Monotonic counter, reset by the sparsify launch each call.
// ---------------------------------------------------------------------------
__device__ __forceinline__ void batch_barrier(unsigned* ctr, unsigned target) {
    __syncthreads();
    if (threadIdx.x == 0) {
        red_add_release_gpu(ctr, 1u);
        while (ld_acquire_gpu(ctr) < target) { /* poll: plain L2 loads */ }
    }
    __syncthreads();
}

// ---------------------------------------------------------------------------
// Sparsify: one block per row, PURE STREAM hot loop (load/count/scan/write —
// nothing else; any extra work here costs 20-100%, proven R12/R13/R14).
// Deterministic compaction (block exclusive scan, no atomics) => fixed column
// order => bitwise-identical result every call. Row-contiguous output.
// Also resets the per-batch barrier counters for the fused kernel.
// ---------------------------------------------------------------------------
__global__ void __launch_bounds__(256) sparsify_kernel(const float4* __restrict__ mask) {
    const int row  = blockIdx.x;
    const int tid  = threadIdx.x;
    const int lane = tid & 31;
    const int wid  = tid >> 5;

    if (row == 0 && tid < BATCH) g_bars[tid] = 0;   // reset barrier counters

    const float4* rp = mask + (size_t)row * (SEQ / 4);

    float4 m[4];
    int v4idx[4];
#pragma unroll
    for (int it = 0; it < 4; it++) {
        v4idx[it] = tid + it * 256;
        m[it] = ldcs_f4(&rp[v4idx[it]]);      // streaming: read-once data
    }

    int count = 0;
#pragma unroll
    for (int it = 0; it < 4; it++) {
        count += (m[it].x != 0.0f) + (m[it].y != 0.0f) +
                 (m[it].z != 0.0f) + (m[it].w != 0.0f);
    }

    // Block-wide exclusive scan
    int inc = count;
#pragma unroll
    for (int o = 1; o < 32; o <<= 1) {
        int n = __shfl_up_sync(0xFFFFFFFFu, inc, o);
        if (lane >= o) inc += n;
    }
    __shared__ int wsum[8];
    if (lane == 31) wsum[wid] = inc;
    __syncthreads();
    if (wid == 0 && lane < 8) {
        int v = wsum[lane];
#pragma unroll
        for (int o = 1; o < 8; o <<= 1) {
            int n = __shfl_up_sync(0xFFu, v, o);
            if (lane >= o) v += n;
        }
        wsum[lane] = v;
    }
    __syncthreads();

    int offset = (inc - count) + (wid ? wsum[wid - 1] : 0);
    int total  = wsum[7];

    uint16_t* out = g_cols + (size_t)row * CAP;
    int pos = offset;
#pragma unroll
    for (int it = 0; it < 4; it++) {
        int base = v4idx[it] * 4;
        if (m[it].x != 0.0f) { if (pos < CAP) out[pos] = (uint16_t)(base + 0); pos++; }
        if (m[it].y != 0.0f) { if (pos < CAP) out[pos] = (uint16_t)(base + 1); pos++; }
        if (m[it].z != 0.0f) { if (pos < CAP) out[pos] = (uint16_t)(base + 2); pos++; }
        if (m[it].w != 0.0f) { if (pos < CAP) out[pos] = (uint16_t)(base + 3); pos++; }
    }

    if (tid == 0) g_cnt[row] = (total < CAP) ? total : CAP;
}

// ---------------------------------------------------------------------------
// Fused integrator: 6 phases (A0..B2), 5 per-batch barriers. 8 threads/row;
// column indices cached in registers (zero per-phase index loads).
// Phase A0 stages from psi_in (launch-visible, plain loads, no barrier).
// ---------------------------------------------------------------------------
__global__ void __launch_bounds__(TPB) fused_steps_kernel(const float2* __restrict__ psi_in,
                                                          float2* __restrict__ out) {
    __shared__ float2 sstate[SEQ];            // 32 KB: this block's batch state

    const int tid   = threadIdx.x;
    const int g     = blockIdx.x * TPB + tid;
    const int row   = g >> 3;                 // 8 threads per row
    const int sub   = g & 7;
    const int batch = row >> 12;              // uniform per block

    const float4* __restrict__ bpsi_in4 = (const float4*)(psi_in + (size_t)batch * SEQ);
    const float4* __restrict__ bpsi4    = (const float4*)(g_psi  + (size_t)batch * SEQ);
    const float4* __restrict__ bstar4   = (const float4*)(g_star + (size_t)batch * SEQ);
    float4* __restrict__ sstate4        = (float4*)sstate;
    unsigned* __restrict__ bar          = &g_bars[batch];

    const int cnt = g_cnt[row];               // prior launch: plain ld OK
    const uint16_t* __restrict__ cols = g_cols + (size_t)row * CAP;

    // Cache this sub-thread's column indices in registers (cnt <= 80 covered)
    int myc[NREG];
#pragma unroll
    for (int k = 0; k < NREG; k++) {
        int i = sub + 8 * k;
        myc[k] = (i < cnt) ? (int)cols[i] : 0;
    }

    float2 p = psi_in[row];
    unsigned bar_target = 0;

#pragma unroll 1
    for (int s = 0; s < 3; s++) {
        // ---------- Phase A: stage state, k1 = force(p), psi_star ----------
        if (s == 0) {
#pragma unroll
            for (int i = 0; i < SEQ / 2 / TPB; i++)
                sstate4[tid + i * TPB] = bpsi_in4[tid + i * TPB];  // launch-visible
        } else {
#pragma unroll
            for (int i = 0; i < SEQ / 2 / TPB; i++)
                sstate4[tid + i * TPB] = ldcg_f4(&bpsi4[tid + i * TPB]);
        }
        __syncthreads();

        float sx = 0.0f, sy = 0.0f;
#pragma unroll
        for (int k = 0; k < NREG; k++) {
            if (sub + 8 * k < cnt) {
                float2 v = sstate[myc[k]];
                sx += v.x; sy += v.y;
            }
        }
        for (int i = sub + 8 * NREG; i < cnt; i += 8) {  // rare tail
            float2 v = sstate[cols[i]];
            sx += v.x; sy += v.y;
        }
        sx += __shfl_xor_sync(0xFFFFFFFFu, sx, 1);
        sy += __shfl_xor_sync(0xFFFFFFFFu, sy, 1);
        sx += __shfl_xor_sync(0xFFFFFFFFu, sx, 2);
        sy += __shfl_xor_sync(0xFFFFFFFFu, sy, 2);
        sx += __shfl_xor_sync(0xFFFFFFFFu, sx, 4);
        sy += __shfl_xor_sync(0xFFFFFFFFu, sy, 4);

        float k1x = sx - p.x, k1y = sy - p.y;
        float r = sqrtf(p.x * p.x + p.y * p.y);
        float stx = p.x + DT_C * k1x;
        float sty = p.y + DT_C * k1y;
        float sn = sqrtf(stx * stx + sty * sty);
        float sc = r / (sn + EPS_C);
        float2 star = make_float2(stx * sc, sty * sc);
        if (sub == 0) g_star[row] = star;

        bar_target += BLK_PER_BATCH;
        batch_barrier(bar, bar_target);   // all same-batch psi_star published

        // ---------- Phase B: stage g_star, k2 = force(star), update p ----------
#pragma unroll
        for (int i = 0; i < SEQ / 2 / TPB; i++)
            sstate4[tid + i * TPB] = ldcg_f4(&bstar4[tid + i * TPB]);
        __syncthreads();

        sx = 0.0f; sy = 0.0f;
#pragma unroll
        for (int k = 0; k < NREG; k++) {
            if (sub + 8 * k < cnt) {
                float2 v = sstate[myc[k]];
                sx += v.x; sy += v.y;
            }
        }
        for (int i = sub + 8 * NREG; i < cnt; i += 8) {      // rare tail
            float2 v = sstate[cols[i]];
            sx += v.x; sy += v.y;
        }
        sx += __shfl_xor_sync(0xFFFFFFFFu, sx, 1);
        sy += __shfl_xor_sync(0xFFFFFFFFu, sy, 1);
        sx += __shfl_xor_sync(0xFFFFFFFFu, sx, 2);
        sy += __shfl_xor_sync(0xFFFFFFFFu, sy, 2);
        sx += __shfl_xor_sync(0xFFFFFFFFu, sx, 4);
        sy += __shfl_xor_sync(0xFFFFFFFFu, sy, 4);

        float k2x = sx - star.x, k2y = sy - star.y;
        float px = p.x + 0.5f * DT_C * (k1x + k2x);
        float py = p.y + 0.5f * DT_C * (k1y + k2y);
        float nn = sqrtf(px * px + py * py);
        float sc2 = r / (nn + EPS_C);
        p = make_float2(px * sc2, py * sc2);

        if (s == 2) {
            if (sub == 0) out[row] = p;        // final result
        } else {
            if (sub == 0) g_psi[row] = p;      // publish for next step
            bar_target += BLK_PER_BATCH;
            batch_barrier(bar, bar_target);
        }
    }
}

extern "C" void kernel_launch(void* const* d_in, const int* in_sizes, int n_in,
                              void* d_out, int out_size) {
    // metadata order: psi (32768 floats), binary_mask (67108864 floats).
    int pi = 0, mi = 1;
    if (n_in >= 2 && in_sizes[0] > in_sizes[1]) { pi = 1; mi = 0; }

    const float2* psi_in = (const float2*)d_in[pi];
    const float4* mask   = (const float4*)d_in[mi];
    float2* out          = (float2*)d_out;

    sparsify_kernel<<<ROWS, 256>>>(mask);
    fused_steps_kernel<<<NBLK, TPB>>>(psi_in, out);
}